// round 2
// baseline (speedup 1.0000x reference)
#include <cuda_runtime.h>
#include <math.h>

#define N_NODES 8192
#define F_IN    512
#define F_OUT   256
#define NEG_MASK (-9e15f)

// ---------------- scratch (device globals; no allocs allowed) ----------------
__device__ float g_Wh[N_NODES * F_OUT];   // 8 MB
__device__ float g_u[N_NODES];            // exp(+0.5*t1_j)
__device__ float g_v[N_NODES];            // exp(+1.0*t1_j)
__device__ float g_p[N_NODES];            // c4 * exp(-0.5*t1_i)
__device__ float g_q[N_NODES];            // c5 * exp(-1.0*t1_i)
__device__ float g_coef[4];               // cA, cB, c4, c5

// ---------------- kernel 1: softmax(Mui) -> coefficients ----------------
__global__ void mui_kernel(const float* __restrict__ Mui) {
    if (threadIdx.x == 0 && blockIdx.x == 0) {
        float m = -INFINITY;
        #pragma unroll
        for (int i = 0; i < 6; i++) m = fmaxf(m, Mui[i]);
        float w[6], s = 0.f;
        #pragma unroll
        for (int i = 0; i < 6; i++) { w[i] = expf(Mui[i] - m); s += w[i]; }
        float inv = 1.f / s;
        #pragma unroll
        for (int i = 0; i < 6; i++) w[i] *= inv;
        g_coef[0] = w[0] + w[1] + w[2] + w[3];                  // cA (on G)
        g_coef[1] = 0.5f * (w[0] + w[1]) + 1.0f * (w[2] + w[3]); // cB (const)
        g_coef[2] = 256.0f * w[4];                               // c4
        g_coef[3] = 256.0f * w[5];                               // c5
    }
}

// ---------------- kernel 2: Wh = h @ W (f32 SGEMM, 128x128x16) ----------------
__global__ __launch_bounds__(256) void wh_gemm(const float* __restrict__ h,
                                               const float* __restrict__ W) {
    __shared__ float sA[16][128];  // A^T tile: [k][m]
    __shared__ float sB[16][128];  // B tile:   [k][n]
    const int tid = threadIdx.x;
    const int tx = tid & 15, ty = tid >> 4;
    const int n0 = blockIdx.x * 128;
    const int m0 = blockIdx.y * 128;

    float acc[8][8];
    #pragma unroll
    for (int i = 0; i < 8; i++)
        #pragma unroll
        for (int j = 0; j < 8; j++) acc[i][j] = 0.f;

    for (int k0 = 0; k0 < F_IN; k0 += 16) {
        #pragma unroll
        for (int l = 0; l < 2; l++) {
            int idx = tid + l * 256;          // 0..511
            // A: 128 rows x 4 float4 along k
            int row = idx >> 2;
            int kq  = idx & 3;
            float4 a = *(const float4*)&h[(size_t)(m0 + row) * F_IN + k0 + kq * 4];
            sA[kq * 4 + 0][row] = a.x;
            sA[kq * 4 + 1][row] = a.y;
            sA[kq * 4 + 2][row] = a.z;
            sA[kq * 4 + 3][row] = a.w;
            // B: 16 rows x 32 float4 along n
            int rowb = idx >> 5;
            int cq   = idx & 31;
            *(float4*)&sB[rowb][cq * 4] =
                *(const float4*)&W[(size_t)(k0 + rowb) * F_OUT + n0 + cq * 4];
        }
        __syncthreads();
        #pragma unroll
        for (int k = 0; k < 16; k++) {
            float a[8], b[8];
            *(float4*)(a)     = *(float4*)&sA[k][ty * 8];
            *(float4*)(a + 4) = *(float4*)&sA[k][ty * 8 + 4];
            *(float4*)(b)     = *(float4*)&sB[k][tx * 8];
            *(float4*)(b + 4) = *(float4*)&sB[k][tx * 8 + 4];
            #pragma unroll
            for (int i = 0; i < 8; i++)
                #pragma unroll
                for (int j = 0; j < 8; j++)
                    acc[i][j] = fmaf(a[i], b[j], acc[i][j]);
        }
        __syncthreads();
    }
    #pragma unroll
    for (int i = 0; i < 8; i++)
        #pragma unroll
        for (int j4 = 0; j4 < 2; j4++)
            *(float4*)&g_Wh[(size_t)(m0 + ty * 8 + i) * F_OUT + n0 + tx * 8 + j4 * 4] =
                *(float4*)&acc[i][j4 * 4];
}

// ---------------- kernel 3: per-node factors ----------------
__global__ void node_prep() {
    int i = blockIdx.x * blockDim.x + threadIdx.x;
    if (i < N_NODES) {
        float wh1 = g_Wh[(size_t)i * F_OUT + 1];
        float t1 = wh1 * wh1;
        g_u[i] = expf(0.5f * t1);
        g_v[i] = expf(t1);
        g_p[i] = g_coef[2] * expf(-0.5f * t1);
        g_q[i] = g_coef[3] * expf(-t1);
    }
}

// ---------------- kernel 4: fused flash attention ----------------
// BM=64 query rows per CTA, BN=64 key cols per tile, D=256.
// Threads: 256 as 16x16. Each thread: S block 4x4 (rows ty*4.., cols tx*4..),
// acc block 4 rows x 4 float4 col-groups (cols cc*64 + tx*4).
#define BM 64
#define BN 64
#define PAD_F4 65  // float4 row stride for Wh tiles (64 + 1 pad)

__global__ __launch_bounds__(256, 1) void flash_kernel(const int* __restrict__ adj,
                                                       float* __restrict__ out) {
    extern __shared__ float smem[];
    float* sWhI   = smem;                         // BM * 260 floats
    float* sWhJ   = sWhI + BM * PAD_F4 * 4;       // BN * 260
    float* sP     = sWhJ + BN * PAD_F4 * 4;       // 64 * 65
    int*   sAdj   = (int*)(sP + 64 * 65);         // 64 * 64
    float* sU     = (float*)(sAdj + 64 * 64);     // 64
    float* sV     = sU + 64;
    float* sPi    = sV + 64;
    float* sQi    = sPi + 64;
    float* sM     = sQi + 64;
    float* sL     = sM + 64;
    float* sScale = sL + 64;
    float* sMnew  = sScale + 64;

    const int tid = threadIdx.x;
    const int tx = tid & 15, ty = tid >> 4;
    const int i0 = blockIdx.x * BM;
    const float cA = g_coef[0], cB = g_coef[1];
    const float NEGINF = __int_as_float(0xff800000u);

    float4* sWhI4 = (float4*)sWhI;
    float4* sWhJ4 = (float4*)sWhJ;
    const float4* Wh4 = (const float4*)g_Wh;

    // load Wh_i tile (once)
    for (int idx = tid; idx < BM * 64; idx += 256) {
        int r = idx >> 6, c4 = idx & 63;
        sWhI4[r * PAD_F4 + c4] = Wh4[(size_t)(i0 + r) * 64 + c4];
    }
    if (tid < BM) {
        sPi[tid] = g_p[i0 + tid];
        sQi[tid] = g_q[i0 + tid];
        sM[tid] = NEGINF;
        sL[tid] = 0.f;
    }
    float4 acc[4][4];
    #pragma unroll
    for (int i = 0; i < 4; i++)
        #pragma unroll
        for (int c = 0; c < 4; c++) acc[i][c] = make_float4(0.f, 0.f, 0.f, 0.f);
    __syncthreads();

    const int4* adj4 = (const int4*)adj;
    int4* sAdj4 = (int4*)sAdj;

    for (int j0 = 0; j0 < N_NODES; j0 += BN) {
        // ---- load key tile ----
        for (int idx = tid; idx < BN * 64; idx += 256) {
            int r = idx >> 6, c4 = idx & 63;
            sWhJ4[r * PAD_F4 + c4] = Wh4[(size_t)(j0 + r) * 64 + c4];
        }
        for (int idx = tid; idx < BM * 16; idx += 256) {
            int r = idx >> 4, c4 = idx & 15;
            sAdj4[r * 16 + c4] = adj4[(size_t)(i0 + r) * (N_NODES / 4) + (j0 >> 2) + c4];
        }
        if (tid < BN) {
            sU[tid] = g_u[j0 + tid];
            sV[tid] = g_v[j0 + tid];
        }
        __syncthreads();

        // ---- S = Wh_i @ Wh_j^T (4x4 per thread) ----
        float s[4][4];
        #pragma unroll
        for (int i = 0; i < 4; i++)
            #pragma unroll
            for (int j = 0; j < 4; j++) s[i][j] = 0.f;
        {
            const float4* ai = sWhI4 + (ty * 4) * PAD_F4;
            const float4* bj = sWhJ4 + (tx * 4) * PAD_F4;
            #pragma unroll 4
            for (int k4 = 0; k4 < 64; k4++) {
                float4 a0 = ai[k4];
                float4 a1 = ai[PAD_F4 + k4];
                float4 a2 = ai[2 * PAD_F4 + k4];
                float4 a3 = ai[3 * PAD_F4 + k4];
                float4 b0 = bj[k4];
                float4 b1 = bj[PAD_F4 + k4];
                float4 b2 = bj[2 * PAD_F4 + k4];
                float4 b3 = bj[3 * PAD_F4 + k4];
                #define DOT4(S, A, B) \
                    S = fmaf(A.x, B.x, fmaf(A.y, B.y, fmaf(A.z, B.z, fmaf(A.w, B.w, S))))
                DOT4(s[0][0], a0, b0); DOT4(s[0][1], a0, b1); DOT4(s[0][2], a0, b2); DOT4(s[0][3], a0, b3);
                DOT4(s[1][0], a1, b0); DOT4(s[1][1], a1, b1); DOT4(s[1][2], a1, b2); DOT4(s[1][3], a1, b3);
                DOT4(s[2][0], a2, b0); DOT4(s[2][1], a2, b1); DOT4(s[2][2], a2, b2); DOT4(s[2][3], a2, b3);
                DOT4(s[3][0], a3, b0); DOT4(s[3][1], a3, b1); DOT4(s[3][2], a3, b2); DOT4(s[3][3], a3, b3);
                #undef DOT4
            }
        }

        // ---- scores + mask + row max ----
        float e[4][4];
        float rowmax[4];
        float u0 = sU[tx * 4 + 0], u1 = sU[tx * 4 + 1], u2 = sU[tx * 4 + 2], u3 = sU[tx * 4 + 3];
        float v0 = sV[tx * 4 + 0], v1 = sV[tx * 4 + 1], v2 = sV[tx * 4 + 2], v3 = sV[tx * 4 + 3];
        #pragma unroll
        for (int i = 0; i < 4; i++) {
            int r = ty * 4 + i;
            int4 mk = sAdj4[r * 16 + tx];
            float pu = sPi[r], qv = sQi[r];
            e[i][0] = (mk.x > 0) ? fmaf(cA, s[i][0], cB) + fmaf(pu, u0, qv * v0) : NEG_MASK;
            e[i][1] = (mk.y > 0) ? fmaf(cA, s[i][1], cB) + fmaf(pu, u1, qv * v1) : NEG_MASK;
            e[i][2] = (mk.z > 0) ? fmaf(cA, s[i][2], cB) + fmaf(pu, u2, qv * v2) : NEG_MASK;
            e[i][3] = (mk.w > 0) ? fmaf(cA, s[i][3], cB) + fmaf(pu, u3, qv * v3) : NEG_MASK;
            float m01 = fmaxf(e[i][0], e[i][1]);
            float m23 = fmaxf(e[i][2], e[i][3]);
            rowmax[i] = fmaxf(m01, m23);
        }
        #pragma unroll
        for (int i = 0; i < 4; i++) {
            #pragma unroll
            for (int off = 8; off >= 1; off >>= 1)
                rowmax[i] = fmaxf(rowmax[i], __shfl_xor_sync(0xffffffffu, rowmax[i], off));
        }
        if (tx == 0) {
            #pragma unroll
            for (int i = 0; i < 4; i++) {
                int r = ty * 4 + i;
                float mo = sM[r];
                float mn = fmaxf(mo, rowmax[i]);
                sMnew[r] = mn;
                sScale[r] = __expf(mo - mn);
            }
        }
        __syncthreads();

        // ---- weights, P tile, row sums, rescale acc ----
        float rowsum[4];
        #pragma unroll
        for (int i = 0; i < 4; i++) {
            int r = ty * 4 + i;
            float mn = sMnew[r];
            float w0 = __expf(e[i][0] - mn);
            float w1 = __expf(e[i][1] - mn);
            float w2 = __expf(e[i][2] - mn);
            float w3 = __expf(e[i][3] - mn);
            float* pr = &sP[r * 65 + tx * 4];
            pr[0] = w0; pr[1] = w1; pr[2] = w2; pr[3] = w3;
            rowsum[i] = (w0 + w1) + (w2 + w3);
        }
        #pragma unroll
        for (int i = 0; i < 4; i++) {
            #pragma unroll
            for (int off = 8; off >= 1; off >>= 1)
                rowsum[i] += __shfl_xor_sync(0xffffffffu, rowsum[i], off);
        }
        #pragma unroll
        for (int i = 0; i < 4; i++) {
            float sc = sScale[ty * 4 + i];
            #pragma unroll
            for (int c = 0; c < 4; c++) {
                acc[i][c].x *= sc; acc[i][c].y *= sc;
                acc[i][c].z *= sc; acc[i][c].w *= sc;
            }
        }
        if (tx == 0) {
            #pragma unroll
            for (int i = 0; i < 4; i++) {
                int r = ty * 4 + i;
                sL[r] = sL[r] * sScale[r] + rowsum[i];
                sM[r] = sMnew[r];
            }
        }
        __syncthreads();  // P + sWhJ ready for PV

        // ---- acc += P @ Wh_j ----
        {
            const float* p0r = &sP[(ty * 4 + 0) * 65];
            const float* p1r = &sP[(ty * 4 + 1) * 65];
            const float* p2r = &sP[(ty * 4 + 2) * 65];
            const float* p3r = &sP[(ty * 4 + 3) * 65];
            #pragma unroll 4
            for (int ss = 0; ss < BN; ss++) {
                float p0 = p0r[ss], p1 = p1r[ss], p2 = p2r[ss], p3 = p3r[ss];
                const float4* wr = sWhJ4 + ss * PAD_F4 + tx;
                #pragma unroll
                for (int cc = 0; cc < 4; cc++) {
                    float4 w = wr[cc * 16];
                    acc[0][cc].x = fmaf(p0, w.x, acc[0][cc].x);
                    acc[0][cc].y = fmaf(p0, w.y, acc[0][cc].y);
                    acc[0][cc].z = fmaf(p0, w.z, acc[0][cc].z);
                    acc[0][cc].w = fmaf(p0, w.w, acc[0][cc].w);
                    acc[1][cc].x = fmaf(p1, w.x, acc[1][cc].x);
                    acc[1][cc].y = fmaf(p1, w.y, acc[1][cc].y);
                    acc[1][cc].z = fmaf(p1, w.z, acc[1][cc].z);
                    acc[1][cc].w = fmaf(p1, w.w, acc[1][cc].w);
                    acc[2][cc].x = fmaf(p2, w.x, acc[2][cc].x);
                    acc[2][cc].y = fmaf(p2, w.y, acc[2][cc].y);
                    acc[2][cc].z = fmaf(p2, w.z, acc[2][cc].z);
                    acc[2][cc].w = fmaf(p2, w.w, acc[2][cc].w);
                    acc[3][cc].x = fmaf(p3, w.x, acc[3][cc].x);
                    acc[3][cc].y = fmaf(p3, w.y, acc[3][cc].y);
                    acc[3][cc].z = fmaf(p3, w.z, acc[3][cc].z);
                    acc[3][cc].w = fmaf(p3, w.w, acc[3][cc].w);
                }
            }
        }
        __syncthreads();  // before overwriting sWhJ / sAdj / sP next iter
    }

    // ---- epilogue: out = elu(acc / l) ----
    float4* out4 = (float4*)out;
    #pragma unroll
    for (int i = 0; i < 4; i++) {
        int r = ty * 4 + i;
        float inv = 1.0f / sL[r];
        #pragma unroll
        for (int cc = 0; cc < 4; cc++) {
            float4 a = acc[i][cc];
            a.x *= inv; a.y *= inv; a.z *= inv; a.w *= inv;
            a.x = (a.x > 0.f) ? a.x : expm1f(a.x);
            a.y = (a.y > 0.f) ? a.y : expm1f(a.y);
            a.z = (a.z > 0.f) ? a.z : expm1f(a.z);
            a.w = (a.w > 0.f) ? a.w : expm1f(a.w);
            out4[(size_t)(i0 + r) * 64 + cc * 16 + tx] = a;
        }
    }
}

// ---------------- launcher ----------------
extern "C" void kernel_launch(void* const* d_in, const int* in_sizes, int n_in,
                              void* d_out, int out_size) {
    const float* h   = (const float*)d_in[0];   // [8192, 512]
    const float* W   = (const float*)d_in[1];   // [512, 256]
    const float* Mui = (const float*)d_in[2];   // [6, 1]
    const int*   adj = (const int*)d_in[3];     // [8192, 8192]
    float* out = (float*)d_out;                 // [8192, 256]

    (void)in_sizes; (void)n_in; (void)out_size;

    const int smem_bytes = (BM * PAD_F4 * 4 + BN * PAD_F4 * 4 + 64 * 65) * 4
                         + 64 * 64 * 4 + 8 * 64 * 4;  // ~168 KB
    cudaFuncSetAttribute(flash_kernel, cudaFuncAttributeMaxDynamicSharedMemorySize,
                         smem_bytes);

    mui_kernel<<<1, 32>>>(Mui);
    wh_gemm<<<dim3(2, 64), 256>>>(h, W);
    node_prep<<<N_NODES / 256, 256>>>();
    flash_kernel<<<N_NODES / BM, 256, smem_bytes>>>(adj, out);
}

// round 3
// speedup vs baseline: 1.5760x; 1.5760x over previous
#include <cuda_runtime.h>
#include <math.h>

#define N_NODES 8192
#define F_IN    512
#define F_OUT   256
#define NEG_MASK (-9e15f)

// ---------------- scratch (device globals; no allocs allowed) ----------------
__device__ float g_Wh[N_NODES * F_OUT];   // 8 MB
__device__ float g_u[N_NODES];            // exp(+0.5*t1_j)
__device__ float g_v[N_NODES];            // exp(+1.0*t1_j)
__device__ float g_p[N_NODES];            // c4 * exp(-0.5*t1_i)
__device__ float g_q[N_NODES];            // c5 * exp(-1.0*t1_i)
__device__ float g_coef[4];               // cA, cB, c4, c5

// ---------------- kernel 1: softmax(Mui) -> coefficients ----------------
__global__ void mui_kernel(const float* __restrict__ Mui) {
    if (threadIdx.x == 0 && blockIdx.x == 0) {
        float m = -INFINITY;
        #pragma unroll
        for (int i = 0; i < 6; i++) m = fmaxf(m, Mui[i]);
        float w[6], s = 0.f;
        #pragma unroll
        for (int i = 0; i < 6; i++) { w[i] = expf(Mui[i] - m); s += w[i]; }
        float inv = 1.f / s;
        #pragma unroll
        for (int i = 0; i < 6; i++) w[i] *= inv;
        g_coef[0] = w[0] + w[1] + w[2] + w[3];                  // cA (on G)
        g_coef[1] = 0.5f * (w[0] + w[1]) + 1.0f * (w[2] + w[3]); // cB (const)
        g_coef[2] = 256.0f * w[4];                               // c4
        g_coef[3] = 256.0f * w[5];                               // c5
    }
}

// ---------------- kernel 2: Wh = h @ W (f32 SGEMM, 128x128x16) ----------------
__global__ __launch_bounds__(256) void wh_gemm(const float* __restrict__ h,
                                               const float* __restrict__ W) {
    __shared__ float sA[16][128];  // A^T tile: [k][m]
    __shared__ float sB[16][128];  // B tile:   [k][n]
    const int tid = threadIdx.x;
    const int tx = tid & 15, ty = tid >> 4;
    const int n0 = blockIdx.x * 128;
    const int m0 = blockIdx.y * 128;

    float acc[8][8];
    #pragma unroll
    for (int i = 0; i < 8; i++)
        #pragma unroll
        for (int j = 0; j < 8; j++) acc[i][j] = 0.f;

    for (int k0 = 0; k0 < F_IN; k0 += 16) {
        #pragma unroll
        for (int l = 0; l < 2; l++) {
            int idx = tid + l * 256;          // 0..511
            // A: 128 rows x 4 float4 along k
            int row = idx >> 2;
            int kq  = idx & 3;
            float4 a = *(const float4*)&h[(size_t)(m0 + row) * F_IN + k0 + kq * 4];
            sA[kq * 4 + 0][row] = a.x;
            sA[kq * 4 + 1][row] = a.y;
            sA[kq * 4 + 2][row] = a.z;
            sA[kq * 4 + 3][row] = a.w;
            // B: 16 rows x 32 float4 along n
            int rowb = idx >> 5;
            int cq   = idx & 31;
            *(float4*)&sB[rowb][cq * 4] =
                *(const float4*)&W[(size_t)(k0 + rowb) * F_OUT + n0 + cq * 4];
        }
        __syncthreads();
        #pragma unroll
        for (int k = 0; k < 16; k++) {
            float a[8], b[8];
            *(float4*)(a)     = *(float4*)&sA[k][ty * 8];
            *(float4*)(a + 4) = *(float4*)&sA[k][ty * 8 + 4];
            *(float4*)(b)     = *(float4*)&sB[k][tx * 8];
            *(float4*)(b + 4) = *(float4*)&sB[k][tx * 8 + 4];
            #pragma unroll
            for (int i = 0; i < 8; i++)
                #pragma unroll
                for (int j = 0; j < 8; j++)
                    acc[i][j] = fmaf(a[i], b[j], acc[i][j]);
        }
        __syncthreads();
    }
    #pragma unroll
    for (int i = 0; i < 8; i++)
        #pragma unroll
        for (int j4 = 0; j4 < 2; j4++)
            *(float4*)&g_Wh[(size_t)(m0 + ty * 8 + i) * F_OUT + n0 + tx * 8 + j4 * 4] =
                *(float4*)&acc[i][j4 * 4];
}

// ---------------- kernel 3: per-node factors ----------------
__global__ void node_prep() {
    int i = blockIdx.x * blockDim.x + threadIdx.x;
    if (i < N_NODES) {
        float wh1 = g_Wh[(size_t)i * F_OUT + 1];
        float t1 = wh1 * wh1;
        g_u[i] = expf(0.5f * t1);
        g_v[i] = expf(t1);
        g_p[i] = g_coef[2] * expf(-0.5f * t1);
        g_q[i] = g_coef[3] * expf(-t1);
    }
}

// ---------------- kernel 4: fused flash attention ----------------
// BM=64 query rows per CTA, BN=64 key cols per tile, D=256.
// Threads: 256 as 16x16. Each thread: S block 4x4 (rows ty*4.., cols tx*4..),
// acc block 4 rows x 4 float4 col-groups (cols cc*64 + tx*4).
#define BM 64
#define BN 64
#define PAD_F4 65  // float4 row stride for Wh tiles (64 + 1 pad)

__global__ __launch_bounds__(256, 1) void flash_kernel(const int* __restrict__ adj,
                                                       float* __restrict__ out) {
    extern __shared__ float smem[];
    float* sWhI   = smem;                         // BM * 260 floats
    float* sWhJ   = sWhI + BM * PAD_F4 * 4;       // BN * 260
    float* sP     = sWhJ + BN * PAD_F4 * 4;       // 64 * 65
    int*   sAdj   = (int*)(sP + 64 * 65);         // 64 * 64
    float* sU     = (float*)(sAdj + 64 * 64);     // 64
    float* sV     = sU + 64;
    float* sPi    = sV + 64;
    float* sQi    = sPi + 64;
    float* sM     = sQi + 64;
    float* sL     = sM + 64;
    float* sScale = sL + 64;
    float* sMnew  = sScale + 64;

    const int tid = threadIdx.x;
    const int tx = tid & 15, ty = tid >> 4;
    const int i0 = blockIdx.x * BM;
    const float cA = g_coef[0], cB = g_coef[1];
    const float NEGINF = __int_as_float(0xff800000u);

    float4* sWhI4 = (float4*)sWhI;
    float4* sWhJ4 = (float4*)sWhJ;
    const float4* Wh4 = (const float4*)g_Wh;

    // load Wh_i tile (once)
    for (int idx = tid; idx < BM * 64; idx += 256) {
        int r = idx >> 6, c4 = idx & 63;
        sWhI4[r * PAD_F4 + c4] = Wh4[(size_t)(i0 + r) * 64 + c4];
    }
    if (tid < BM) {
        sPi[tid] = g_p[i0 + tid];
        sQi[tid] = g_q[i0 + tid];
        sM[tid] = NEGINF;
        sL[tid] = 0.f;
    }
    float4 acc[4][4];
    #pragma unroll
    for (int i = 0; i < 4; i++)
        #pragma unroll
        for (int c = 0; c < 4; c++) acc[i][c] = make_float4(0.f, 0.f, 0.f, 0.f);
    __syncthreads();

    const int4* adj4 = (const int4*)adj;
    int4* sAdj4 = (int4*)sAdj;

    for (int j0 = 0; j0 < N_NODES; j0 += BN) {
        // ---- load key tile ----
        for (int idx = tid; idx < BN * 64; idx += 256) {
            int r = idx >> 6, c4 = idx & 63;
            sWhJ4[r * PAD_F4 + c4] = Wh4[(size_t)(j0 + r) * 64 + c4];
        }
        for (int idx = tid; idx < BM * 16; idx += 256) {
            int r = idx >> 4, c4 = idx & 15;
            sAdj4[r * 16 + c4] = adj4[(size_t)(i0 + r) * (N_NODES / 4) + (j0 >> 2) + c4];
        }
        if (tid < BN) {
            sU[tid] = g_u[j0 + tid];
            sV[tid] = g_v[j0 + tid];
        }
        __syncthreads();

        // ---- S = Wh_i @ Wh_j^T (4x4 per thread) ----
        float s[4][4];
        #pragma unroll
        for (int i = 0; i < 4; i++)
            #pragma unroll
            for (int j = 0; j < 4; j++) s[i][j] = 0.f;
        {
            const float4* ai = sWhI4 + (ty * 4) * PAD_F4;
            const float4* bj = sWhJ4 + (tx * 4) * PAD_F4;
            #pragma unroll 4
            for (int k4 = 0; k4 < 64; k4++) {
                float4 a0 = ai[k4];
                float4 a1 = ai[PAD_F4 + k4];
                float4 a2 = ai[2 * PAD_F4 + k4];
                float4 a3 = ai[3 * PAD_F4 + k4];
                float4 b0 = bj[k4];
                float4 b1 = bj[PAD_F4 + k4];
                float4 b2 = bj[2 * PAD_F4 + k4];
                float4 b3 = bj[3 * PAD_F4 + k4];
                #define DOT4(S, A, B) \
                    S = fmaf(A.x, B.x, fmaf(A.y, B.y, fmaf(A.z, B.z, fmaf(A.w, B.w, S))))
                DOT4(s[0][0], a0, b0); DOT4(s[0][1], a0, b1); DOT4(s[0][2], a0, b2); DOT4(s[0][3], a0, b3);
                DOT4(s[1][0], a1, b0); DOT4(s[1][1], a1, b1); DOT4(s[1][2], a1, b2); DOT4(s[1][3], a1, b3);
                DOT4(s[2][0], a2, b0); DOT4(s[2][1], a2, b1); DOT4(s[2][2], a2, b2); DOT4(s[2][3], a2, b3);
                DOT4(s[3][0], a3, b0); DOT4(s[3][1], a3, b1); DOT4(s[3][2], a3, b2); DOT4(s[3][3], a3, b3);
                #undef DOT4
            }
        }

        // ---- scores + mask + row max ----
        float e[4][4];
        float rowmax[4];
        float u0 = sU[tx * 4 + 0], u1 = sU[tx * 4 + 1], u2 = sU[tx * 4 + 2], u3 = sU[tx * 4 + 3];
        float v0 = sV[tx * 4 + 0], v1 = sV[tx * 4 + 1], v2 = sV[tx * 4 + 2], v3 = sV[tx * 4 + 3];
        #pragma unroll
        for (int i = 0; i < 4; i++) {
            int r = ty * 4 + i;
            int4 mk = sAdj4[r * 16 + tx];
            float pu = sPi[r], qv = sQi[r];
            e[i][0] = (mk.x > 0) ? fmaf(cA, s[i][0], cB) + fmaf(pu, u0, qv * v0) : NEG_MASK;
            e[i][1] = (mk.y > 0) ? fmaf(cA, s[i][1], cB) + fmaf(pu, u1, qv * v1) : NEG_MASK;
            e[i][2] = (mk.z > 0) ? fmaf(cA, s[i][2], cB) + fmaf(pu, u2, qv * v2) : NEG_MASK;
            e[i][3] = (mk.w > 0) ? fmaf(cA, s[i][3], cB) + fmaf(pu, u3, qv * v3) : NEG_MASK;
            float m01 = fmaxf(e[i][0], e[i][1]);
            float m23 = fmaxf(e[i][2], e[i][3]);
            rowmax[i] = fmaxf(m01, m23);
        }
        #pragma unroll
        for (int i = 0; i < 4; i++) {
            #pragma unroll
            for (int off = 8; off >= 1; off >>= 1)
                rowmax[i] = fmaxf(rowmax[i], __shfl_xor_sync(0xffffffffu, rowmax[i], off));
        }
        if (tx == 0) {
            #pragma unroll
            for (int i = 0; i < 4; i++) {
                int r = ty * 4 + i;
                float mo = sM[r];
                float mn = fmaxf(mo, rowmax[i]);
                sMnew[r] = mn;
                sScale[r] = __expf(mo - mn);
            }
        }
        __syncthreads();

        // ---- weights, P tile, row sums, rescale acc ----
        float rowsum[4];
        #pragma unroll
        for (int i = 0; i < 4; i++) {
            int r = ty * 4 + i;
            float mn = sMnew[r];
            float w0 = __expf(e[i][0] - mn);
            float w1 = __expf(e[i][1] - mn);
            float w2 = __expf(e[i][2] - mn);
            float w3 = __expf(e[i][3] - mn);
            float* pr = &sP[r * 65 + tx * 4];
            pr[0] = w0; pr[1] = w1; pr[2] = w2; pr[3] = w3;
            rowsum[i] = (w0 + w1) + (w2 + w3);
        }
        #pragma unroll
        for (int i = 0; i < 4; i++) {
            #pragma unroll
            for (int off = 8; off >= 1; off >>= 1)
                rowsum[i] += __shfl_xor_sync(0xffffffffu, rowsum[i], off);
        }
        #pragma unroll
        for (int i = 0; i < 4; i++) {
            float sc = sScale[ty * 4 + i];
            #pragma unroll
            for (int c = 0; c < 4; c++) {
                acc[i][c].x *= sc; acc[i][c].y *= sc;
                acc[i][c].z *= sc; acc[i][c].w *= sc;
            }
        }
        if (tx == 0) {
            #pragma unroll
            for (int i = 0; i < 4; i++) {
                int r = ty * 4 + i;
                sL[r] = sL[r] * sScale[r] + rowsum[i];
                sM[r] = sMnew[r];
            }
        }
        __syncthreads();  // P + sWhJ ready for PV

        // ---- acc += P @ Wh_j ----
        {
            const float* p0r = &sP[(ty * 4 + 0) * 65];
            const float* p1r = &sP[(ty * 4 + 1) * 65];
            const float* p2r = &sP[(ty * 4 + 2) * 65];
            const float* p3r = &sP[(ty * 4 + 3) * 65];
            #pragma unroll 4
            for (int ss = 0; ss < BN; ss++) {
                float p0 = p0r[ss], p1 = p1r[ss], p2 = p2r[ss], p3 = p3r[ss];
                const float4* wr = sWhJ4 + ss * PAD_F4 + tx;
                #pragma unroll
                for (int cc = 0; cc < 4; cc++) {
                    float4 w = wr[cc * 16];
                    acc[0][cc].x = fmaf(p0, w.x, acc[0][cc].x);
                    acc[0][cc].y = fmaf(p0, w.y, acc[0][cc].y);
                    acc[0][cc].z = fmaf(p0, w.z, acc[0][cc].z);
                    acc[0][cc].w = fmaf(p0, w.w, acc[0][cc].w);
                    acc[1][cc].x = fmaf(p1, w.x, acc[1][cc].x);
                    acc[1][cc].y = fmaf(p1, w.y, acc[1][cc].y);
                    acc[1][cc].z = fmaf(p1, w.z, acc[1][cc].z);
                    acc[1][cc].w = fmaf(p1, w.w, acc[1][cc].w);
                    acc[2][cc].x = fmaf(p2, w.x, acc[2][cc].x);
                    acc[2][cc].y = fmaf(p2, w.y, acc[2][cc].y);
                    acc[2][cc].z = fmaf(p2, w.z, acc[2][cc].z);
                    acc[2][cc].w = fmaf(p2, w.w, acc[2][cc].w);
                    acc[3][cc].x = fmaf(p3, w.x, acc[3][cc].x);
                    acc[3][cc].y = fmaf(p3, w.y, acc[3][cc].y);
                    acc[3][cc].z = fmaf(p3, w.z, acc[3][cc].z);
                    acc[3][cc].w = fmaf(p3, w.w, acc[3][cc].w);
                }
            }
        }
        __syncthreads();  // before overwriting sWhJ / sAdj / sP next iter
    }

    // ---- epilogue: out = elu(acc / l) ----
    float4* out4 = (float4*)out;
    #pragma unroll
    for (int i = 0; i < 4; i++) {
        int r = ty * 4 + i;
        float inv = 1.0f / sL[r];
        #pragma unroll
        for (int cc = 0; cc < 4; cc++) {
            float4 a = acc[i][cc];
            a.x *= inv; a.y *= inv; a.z *= inv; a.w *= inv;
            a.x = (a.x > 0.f) ? a.x : expm1f(a.x);
            a.y = (a.y > 0.f) ? a.y : expm1f(a.y);
            a.z = (a.z > 0.f) ? a.z : expm1f(a.z);
            a.w = (a.w > 0.f) ? a.w : expm1f(a.w);
            out4[(size_t)(i0 + r) * 64 + cc * 16 + tx] = a;
        }
    }
}

// ---------------- launcher ----------------
extern "C" void kernel_launch(void* const* d_in, const int* in_sizes, int n_in,
                              void* d_out, int out_size) {
    const float* h   = (const float*)d_in[0];   // [8192, 512]
    const float* W   = (const float*)d_in[1];   // [512, 256]
    const float* Mui = (const float*)d_in[2];   // [6, 1]
    const int*   adj = (const int*)d_in[3];     // [8192, 8192]
    float* out = (float*)d_out;                 // [8192, 256]

    (void)in_sizes; (void)n_in; (void)out_size;

    const int smem_bytes = (BM * PAD_F4 * 4 + BN * PAD_F4 * 4 + 64 * 65) * 4
                         + 64 * 64 * 4 + 8 * 64 * 4;  // ~168 KB
    cudaFuncSetAttribute(flash_kernel, cudaFuncAttributeMaxDynamicSharedMemorySize,
                         smem_bytes);

    mui_kernel<<<1, 32>>>(Mui);
    wh_gemm<<<dim3(2, 64), 256>>>(h, W);
    node_prep<<<N_NODES / 256, 256>>>();
    flash_kernel<<<N_NODES / BM, 256, smem_bytes>>>(adj, out);
}